// round 13
// baseline (speedup 1.0000x reference)
#include <cuda_runtime.h>

// Delta differential encoding with residual carry + floor quantization.
// x: [B=32, C=2048, T=512] float32, contiguous in T.
//
// 2048 single-warp blocks, 32 rows/warp, warp-private smem staging,
// CHUNK=32, DEPTH=3 cp.async pipeline. This round: the cooperative store
// of chunk k-1 is fused into the same barrier-free region as chunk k's
// carry chain, so its LDS/STG issue in the chain's dead slots instead of
// a separate serialized phase. cp.async issue moved after the end barrier
// to preserve the buffer-reuse hazard ordering.

#define SCALE 64.0f
#define INV_SCALE (1.0f / 64.0f)
#define T_LEN 512
#define N_ROWS (32 * 2048)

#define RPW 32             // rows per warp (one per lane)
#define RPB 32             // 1 warp per block
#define CHUNK 32           // floats per row per chunk (= one 128B line)
#define PAD 36             // padded row stride in floats (conflict-free, 16B aligned)
#define NCHUNK (T_LEN / CHUNK)   // 16
#define F4_PER_LANE 8            // 32 rows * 8 float4 / 32 lanes
#define DEPTH 3

#define BUF_FLOATS (RPW * PAD)           // 1152 floats
#define SMEM_FLOATS (DEPTH * BUF_FLOATS)
#define SMEM_BYTES (SMEM_FLOATS * 4)     // 13824 B -> 14 blocks/SM, single wave

// One element of the speculative carry chain (~8 cyc critical path).
#define ELEM(dcur, xprev, xcur, odst)                         \
    {                                                          \
        bool  keep = fabsf(dcur) >= thr;                       \
        float y    = keep ? dcur : 0.0f;                       \
        odst       = floorf(y * SCALE) * INV_SCALE;            \
        float dxn  = (xcur) - (xprev);      /* off-chain */    \
        float dc   = dxn + dcur;            /* starts at d */  \
        dcur       = keep ? dxn : dc;                          \
    }

__global__ void __launch_bounds__(RPB) delta_kernel(
    const float* __restrict__ x,
    const float* __restrict__ thr_in,
    float* __restrict__ out)
{
    extern __shared__ float smem[];

    const int lane = threadIdx.x & 31;

    float* bufs[DEPTH] = { smem, smem + BUF_FLOATS, smem + 2 * BUF_FLOATS };

    const size_t rowbase = (size_t)blockIdx.x * RPW;
    const float* gx = x   + rowbase * T_LEN;
    float*       gy = out + rowbase * T_LEN;

    const float thr = fmaxf(__ldg(thr_in), INV_SCALE);

    // Coalesced async load of one chunk: 8 consecutive lanes cover one row's
    // 128B line; 8 iterations cover 32 rows.
    auto issue_chunk = [&](float* sbuf, int k) {
        const float* gsrc = gx + (size_t)k * CHUNK;
#pragma unroll
        for (int i = 0; i < F4_PER_LANE; ++i) {
            int f   = lane + 32 * i;    // 0..255
            int row = f >> 3;           // 0..31
            int t4  = f & 7;            // 0..7
            const float* src = gsrc + (size_t)row * T_LEN + t4 * 4;
            unsigned saddr = (unsigned)__cvta_generic_to_shared(sbuf + row * PAD + t4 * 4);
            asm volatile("cp.async.cg.shared.global [%0], [%1], 16;"
                         :: "r"(saddr), "l"(src));
        }
        asm volatile("cp.async.commit_group;");
    };

    // Coalesced cooperative store of one chunk from its smem buffer.
    auto store_chunk = [&](const float* sbuf, int k) {
        float* gdst = gy + (size_t)k * CHUNK;
#pragma unroll
        for (int i = 0; i < F4_PER_LANE; ++i) {
            int f   = lane + 32 * i;
            int row = f >> 3;
            int t4  = f & 7;
            *reinterpret_cast<float4*>(gdst + (size_t)row * T_LEN + t4 * 4) =
                *reinterpret_cast<const float4*>(sbuf + row * PAD + t4 * 4);
        }
    };

    // Prologue: fill two stages.
    issue_chunk(bufs[0], 0);
    issue_chunk(bufs[1], 1);

    float pre = 0.0f;  // x[t-1] at chunk boundary
    float r   = 0.0f;  // residual carry at chunk boundary

#pragma unroll 1
    for (int k = 0; k < NCHUNK; ++k) {
        float* sbuf = bufs[k % DEPTH];

        // Issued chunks so far: 0..k+1. Chunk k complete once <=1 group
        // remains outstanding.
        if (k + 1 < NCHUNK) {
            asm volatile("cp.async.wait_group 1;");
        } else {
            asm volatile("cp.async.wait_group 0;");
        }
        __syncwarp();   // chunk k loaded; chunk k-1 outputs visible (prev barrier)

        // ===== barrier-free region: chain(k) + store(k-1) interleave =====
        {
            float4* myrow = reinterpret_cast<float4*>(sbuf + lane * PAD);

            float4 v = myrow[0];
            float  d = (v.x - pre) + r;       // chain state = current delta

#pragma unroll
            for (int j4 = 0; j4 < CHUNK / 4; ++j4) {
                float4 vn = (j4 + 1 < CHUNK / 4) ? myrow[j4 + 1] : v;

                float4 o4;
                ELEM(d, v.x, v.y, o4.x);
                ELEM(d, v.y, v.z, o4.y);
                ELEM(d, v.z, v.w, o4.z);
                if (j4 + 1 < CHUNK / 4) {
                    ELEM(d, v.w, vn.x, o4.w);
                } else {
                    bool  keep = fabsf(d) >= thr;
                    float y    = keep ? d : 0.0f;
                    o4.w = floorf(y * SCALE) * INV_SCALE;
                    r    = keep ? 0.0f : d;
                    pre  = v.w;
                }
                myrow[j4] = o4;   // fused in-place writeback
                v = vn;
            }

            if (k > 0) {
                // Store previous chunk; issues in the chain's idle slots.
                store_chunk(bufs[(k - 1) % DEPTH], k - 1);
            }
        }
        __syncwarp();   // k's outputs visible; (k-1)'s store-LDS reads done

        // Refill the buffer just freed by store(k-1): (k+2)%3 == (k-1)%3.
        if (k + 2 < NCHUNK) {
            issue_chunk(bufs[(k + 2) % DEPTH], k + 2);
        }
    }

    // Epilogue: store the last chunk.
    store_chunk(bufs[(NCHUNK - 1) % DEPTH], NCHUNK - 1);
}

extern "C" void kernel_launch(void* const* d_in, const int* in_sizes, int n_in,
                              void* d_out, int out_size)
{
    const float* x   = (const float*)d_in[0];
    const float* thr = (const float*)d_in[1];
    float* out       = (float*)d_out;

    const int blocks = N_ROWS / RPW;   // 2048 one-warp blocks
    delta_kernel<<<blocks, RPB, SMEM_BYTES>>>(x, thr, out);
}

// round 14
// speedup vs baseline: 1.0561x; 1.0561x over previous
#include <cuda_runtime.h>

// Delta differential encoding with residual carry + floor quantization.
// x: [B=32, C=2048, T=512] float32, contiguous in T.
//
// FINAL (R12 configuration — best measured kernel duration, 43.97us):
//  - 2048 single-warp blocks, 32 rows/warp (all lanes compute; ~1% SM imbalance)
//  - warp-private smem staging, CHUNK=32 (one 128B line/row), DEPTH=3 cp.async
//    pipeline with refill issued BEFORE the wait (2 chunks always in flight)
//  - slim streaming inner loop: one-ahead LDS prefetch, speculative carry
//    chain (~8 cyc/element critical path), fused in-place writeback
//  - fully coalesced global traffic via cooperative float4 patterns

#define SCALE 64.0f
#define INV_SCALE (1.0f / 64.0f)
#define T_LEN 512
#define N_ROWS (32 * 2048)

#define RPW 32             // rows per warp (one per lane)
#define RPB 32             // 1 warp per block
#define CHUNK 32           // floats per row per chunk (= one 128B line)
#define PAD 36             // padded row stride in floats (conflict-free, 16B aligned)
#define NCHUNK (T_LEN / CHUNK)   // 16
#define F4_PER_LANE 8            // 32 rows * 8 float4 / 32 lanes
#define DEPTH 3

#define BUF_FLOATS (RPW * PAD)           // 1152 floats
#define SMEM_FLOATS (DEPTH * BUF_FLOATS)
#define SMEM_BYTES (SMEM_FLOATS * 4)     // 13824 B -> 14 blocks/SM, single wave

// One element of the speculative carry chain (~8 cyc critical path):
// the FSETP on d and the candidate FADD run in parallel; FSEL resolves.
#define ELEM(dcur, xprev, xcur, odst)                         \
    {                                                          \
        bool  keep = fabsf(dcur) >= thr;                       \
        float y    = keep ? dcur : 0.0f;                       \
        odst       = floorf(y * SCALE) * INV_SCALE;            \
        float dxn  = (xcur) - (xprev);      /* off-chain */    \
        float dc   = dxn + dcur;            /* starts at d */  \
        dcur       = keep ? dxn : dc;                          \
    }

__global__ void __launch_bounds__(RPB) delta_kernel(
    const float* __restrict__ x,
    const float* __restrict__ thr_in,
    float* __restrict__ out)
{
    extern __shared__ float smem[];

    const int lane = threadIdx.x & 31;

    float* bufs[DEPTH] = { smem, smem + BUF_FLOATS, smem + 2 * BUF_FLOATS };

    const size_t rowbase = (size_t)blockIdx.x * RPW;
    const float* gx = x   + rowbase * T_LEN;
    float*       gy = out + rowbase * T_LEN;

    const float thr = fmaxf(__ldg(thr_in), INV_SCALE);

    // Coalesced async load of one chunk: 8 consecutive lanes cover one row's
    // 128B line; 8 iterations cover 32 rows.
    auto issue_chunk = [&](float* sbuf, int k) {
        const float* gsrc = gx + (size_t)k * CHUNK;
#pragma unroll
        for (int i = 0; i < F4_PER_LANE; ++i) {
            int f   = lane + 32 * i;    // 0..255
            int row = f >> 3;           // 0..31
            int t4  = f & 7;            // 0..7
            const float* src = gsrc + (size_t)row * T_LEN + t4 * 4;
            unsigned saddr = (unsigned)__cvta_generic_to_shared(sbuf + row * PAD + t4 * 4);
            asm volatile("cp.async.cg.shared.global [%0], [%1], 16;"
                         :: "r"(saddr), "l"(src));
        }
        asm volatile("cp.async.commit_group;");
    };

    // Prologue: fill two stages.
    issue_chunk(bufs[0], 0);
    issue_chunk(bufs[1], 1);

    float pre = 0.0f;  // x[t-1] at chunk boundary
    float r   = 0.0f;  // residual carry at chunk boundary

#pragma unroll 1
    for (int k = 0; k < NCHUNK; ++k) {
        float* sbuf = bufs[k % DEPTH];

        if (k + 2 < NCHUNK) {
            issue_chunk(bufs[(k + 2) % DEPTH], k + 2);
            asm volatile("cp.async.wait_group 2;");
        } else if (k + 1 < NCHUNK) {
            asm volatile("cp.async.wait_group 1;");
        } else {
            asm volatile("cp.async.wait_group 0;");
        }
        __syncwarp();   // chunk k visible warp-wide

        // ---- per-row sequential work: every lane owns one row ----
        {
            float4* myrow = reinterpret_cast<float4*>(sbuf + lane * PAD);

            float4 v = myrow[0];
            float  d = (v.x - pre) + r;       // chain state = current delta

#pragma unroll
            for (int j4 = 0; j4 < CHUNK / 4; ++j4) {
                // Prefetch next float4 while this one's chain runs.
                float4 vn = (j4 + 1 < CHUNK / 4) ? myrow[j4 + 1] : v;

                float4 o4;
                ELEM(d, v.x, v.y, o4.x);
                ELEM(d, v.y, v.z, o4.y);
                ELEM(d, v.z, v.w, o4.z);
                if (j4 + 1 < CHUNK / 4) {
                    ELEM(d, v.w, vn.x, o4.w);
                } else {
                    // last element of chunk: emit output, update carries
                    bool  keep = fabsf(d) >= thr;
                    float y    = keep ? d : 0.0f;
                    o4.w = floorf(y * SCALE) * INV_SCALE;
                    r    = keep ? 0.0f : d;
                    pre  = v.w;
                }
                myrow[j4] = o4;   // fused in-place writeback
                v = vn;
            }
        }
        __syncwarp();   // outputs in place before cooperative store

        // ---- coalesced cooperative store of this chunk ----
        float* gdst = gy + (size_t)k * CHUNK;
#pragma unroll
        for (int i = 0; i < F4_PER_LANE; ++i) {
            int f   = lane + 32 * i;
            int row = f >> 3;
            int t4  = f & 7;
            *reinterpret_cast<float4*>(gdst + (size_t)row * T_LEN + t4 * 4) =
                *reinterpret_cast<const float4*>(sbuf + row * PAD + t4 * 4);
        }
        __syncwarp();   // store reads done before chunk k+3's cp.async reuses sbuf
    }
}

extern "C" void kernel_launch(void* const* d_in, const int* in_sizes, int n_in,
                              void* d_out, int out_size)
{
    const float* x   = (const float*)d_in[0];
    const float* thr = (const float*)d_in[1];
    float* out       = (float*)d_out;

    const int blocks = N_ROWS / RPW;   // 2048 one-warp blocks
    delta_kernel<<<blocks, RPB, SMEM_BYTES>>>(x, thr, out);
}